// round 16
// baseline (speedup 1.0000x reference)
#include <cuda_runtime.h>
#include <cuda_bf16.h>
#include <cuda_fp16.h>
#include <mma.h>
#include <cstdint>

#define BATCH 512
#define TT 365
#define DD 256
#define NSTEPS 16
#define NB 512   // decode grid size (== BATCH)

// ---------------- scratch (device globals; no allocation allowed) ----------------
__device__ __nv_bfloat16 g_x0h[BATCH * 608], g_x0l[BATCH * 608];
__device__ __nv_bfloat16 g_a1h[BATCH * 512], g_a1l[BATCH * 512];
__device__ __nv_bfloat16 g_a2h[BATCH * 384], g_a2l[BATCH * 384];
__device__ float g_state[BATCH * 512];                       // [h | c] fp32
__device__ __half g_encproj[(size_t)TT * BATCH * 128];       // [B,T,128] fp16
__device__ __half g_enc16[(size_t)TT * BATCH * 256];         // [B,T,256] fp16
__device__ __nv_bfloat16 g_xh_hi[BATCH * 512], g_xh_lo[BATCH * 512];   // [inp|h]
__device__ __nv_bfloat16 g_Wg_hi[512 * 1024], g_Wg_lo[512 * 1024];     // [Wih^T;Whh^T]
__device__ __nv_bfloat16 g_wc1h[608 * 512], g_wc1l[608 * 512];
__device__ __nv_bfloat16 g_wc2h[512 * 384], g_wc2l[512 * 384];
__device__ __nv_bfloat16 g_wc3h[384 * 512], g_wc3l[384 * 512];
__device__ __nv_bfloat16 g_wt1h[256 * 128], g_wt1l[256 * 128];
__device__ float g_bg[1024];
__device__ float g_gates[BATCH * 1024];
__device__ __nv_bfloat16 g_outs_h[NSTEPS * BATCH * 256], g_outs_l[NSTEPS * BATCH * 256];
__device__ float g_td1[NSTEPS * BATCH * 128];

// grid barrier state
__device__ unsigned g_bar_cnt;
__device__ volatile unsigned g_bar_gen;

__device__ __forceinline__ float sigf(float x) { return 1.0f / (1.0f + expf(-x)); }

__device__ __forceinline__ void split2(float v, __nv_bfloat16& hi, __nv_bfloat16& lo) {
    hi = __float2bfloat16(v);
    lo = __float2bfloat16(v - __bfloat162float(hi));
}

// ---------------- grid-wide barrier (all NB blocks co-resident) ----------------
__device__ __forceinline__ void gridbar() {
    __threadfence();
    __syncthreads();
    if (threadIdx.x == 0) {
        unsigned gen = g_bar_gen;
        if (atomicInc(&g_bar_cnt, NB - 1) == NB - 1) {
            __threadfence();
            g_bar_gen = gen + 1;
        } else {
            while (g_bar_gen == gen) __nanosleep(128);
        }
        __threadfence();
    }
    __syncthreads();
}

// ======== per-block 16x64 split-bf16 warp-tile GEMM (global operands, L2-hot) ========
// 8 warps: q = warp&3 -> 16-col slice, h = warp>>2 -> K half. sred = 8*256 floats smem.
template <int ACT>
__device__ void gemm_tile(const __nv_bfloat16* __restrict__ Ah, const __nv_bfloat16* __restrict__ Al,
                          const __nv_bfloat16* __restrict__ Wh, const __nv_bfloat16* __restrict__ Wl,
                          const float* __restrict__ bias, float* __restrict__ Cf,
                          __nv_bfloat16* __restrict__ Chi, __nv_bfloat16* __restrict__ Clo,
                          int m0, int n0, int N, int K, float* sred) {
    using namespace nvcuda;
    const int warp = threadIdx.x >> 5;
    const int q = warp & 3, h = warp >> 2;
    const int n1 = n0 + q * 16;
    const int khalf = K >> 1;
    const int kbeg = h * khalf;
    wmma::fragment<wmma::accumulator, 16, 16, 16, float> acc;
    wmma::fill_fragment(acc, 0.0f);
    for (int k = kbeg; k < kbeg + khalf; k += 16) {
        wmma::fragment<wmma::matrix_a, 16, 16, 16, __nv_bfloat16, wmma::row_major> fah, fal;
        wmma::fragment<wmma::matrix_b, 16, 16, 16, __nv_bfloat16, wmma::row_major> fbh, fbl;
        wmma::load_matrix_sync(fah, Ah + (size_t)m0 * K + k, K);
        wmma::load_matrix_sync(fal, Al + (size_t)m0 * K + k, K);
        wmma::load_matrix_sync(fbh, Wh + (size_t)k * N + n1, N);
        wmma::load_matrix_sync(fbl, Wl + (size_t)k * N + n1, N);
        wmma::mma_sync(acc, fah, fbh, acc);
        wmma::mma_sync(acc, fah, fbl, acc);
        wmma::mma_sync(acc, fal, fbh, acc);
    }
    wmma::store_matrix_sync(sred + warp * 256, acc, 16, wmma::mem_row_major);
    __syncthreads();
    for (int idx = threadIdx.x; idx < 1024; idx += 256) {
        const int r = idx >> 6, c = idx & 63;
        const int qq = c >> 4, cc = c & 15;
        float v = sred[qq * 256 + r * 16 + cc] + sred[(4 + qq) * 256 + r * 16 + cc];
        if (bias) v += bias[n0 + c];
        if (ACT) v = fmaxf(v, 0.0f);
        const size_t off = (size_t)(m0 + r) * N + n0 + c;
        if (Cf) Cf[off] = v;
        if (Chi) {
            __nv_bfloat16 hi, lo;
            split2(v, hi, lo);
            Chi[off] = hi;
            Clo[off] = lo;
        }
    }
    __syncthreads();
}

// =============================== THE persistent decode kernel ===============================
__global__ void __launch_bounds__(256, 4)
decode_kernel(const float* __restrict__ Wa1s, const float* __restrict__ ba1,
              const float* __restrict__ Wa2, const float* __restrict__ bc1,
              const float* __restrict__ bc2, const float* __restrict__ bc3,
              const float* __restrict__ bt1, const float* __restrict__ Wt2,
              const float* __restrict__ bt2, float* __restrict__ out) {
    const int blk = blockIdx.x;
    const int tid = threadIdx.x;
    const int warp = tid >> 5;
    const int lane = tid & 31;

    __shared__ float sred[8 * 256];      // gemm reduction (8 KB)
    __shared__ float s_state[512];
    __shared__ float s_sp[128];
    __shared__ float s_w2[128];
    __shared__ float s_sc[368];
    __shared__ float red[256];
    __shared__ float part[4][256];

    // ---- ct chain: ct1 (512x512 K=608 relu), ct2 (512x384 K=512 relu), ct3 (512x512 K=384) ----
    if (blk < 256) {
        const int m0 = (blk >> 3) * 16, n0 = (blk & 7) * 64;
        gemm_tile<1>(g_x0h, g_x0l, g_wc1h, g_wc1l, bc1, nullptr, g_a1h, g_a1l,
                     m0, n0, 512, 608, sred);
    }
    gridbar();
    if (blk < 192) {
        const int m0 = (blk / 6) * 16, n0 = (blk % 6) * 64;
        gemm_tile<1>(g_a1h, g_a1l, g_wc2h, g_wc2l, bc2, nullptr, g_a2h, g_a2l,
                     m0, n0, 384, 512, sred);
    }
    gridbar();
    if (blk < 256) {
        const int m0 = (blk >> 3) * 16, n0 = (blk & 7) * 64;
        gemm_tile<0>(g_a2h, g_a2l, g_wc3h, g_wc3l, bc3, g_state, nullptr, nullptr,
                     m0, n0, 512, 384, sred);
    }
    gridbar();

    // ---- 16 decode steps ----
    const int b = blk;  // attn block == batch row
    for (int step = 0; step < NSTEPS; step++) {
        // === attn phase (incl. fused LSTM cell for step-1) ===
        if (step > 0) {
            const int j = tid;
            const float* gb = g_gates + (size_t)b * 1024;
            float gi = gb[j] + g_bg[j];
            float gf = gb[256 + j] + g_bg[256 + j];
            float gg = gb[512 + j] + g_bg[512 + j];
            float go = gb[768 + j] + g_bg[768 + j];
            float c = g_state[b * 512 + 256 + j];
            float cn = sigf(gf) * c + sigf(gi) * tanhf(gg);
            float hn = sigf(go) * tanhf(cn);
            s_state[j] = hn;
            s_state[256 + j] = cn;
            g_state[b * 512 + j] = hn;
            g_state[b * 512 + 256 + j] = cn;
            const size_t o = (size_t)(step - 1) * BATCH * 256 + b * 256 + j;
            split2(hn, g_outs_h[o], g_outs_l[o]);
        } else {
            s_state[tid] = g_state[b * 512 + tid];
            s_state[256 + tid] = g_state[b * 512 + 256 + tid];
        }
        if (tid < 128) s_w2[tid] = Wa2[tid];
        __syncthreads();

        // phase 0: sproj[d] = sum_k state[k] * Wa1s[k,d] + ba1[d]
        {
            const int d = tid & 127;
            const int half_ = tid >> 7;
            const float* wp = Wa1s + (size_t)(half_ * 256) * 128 + d;
            const float* st = s_state + half_ * 256;
            float acc = 0.0f;
#pragma unroll 16
            for (int k = 0; k < 256; k++) acc += st[k] * wp[(size_t)k * 128];
            red[tid] = acc;
            __syncthreads();
            if (tid < 128) s_sp[tid] = red[tid] + red[tid + 128] + ba1[tid];
            __syncthreads();
        }

        // phase 1: scores
        {
            const float4 sp = reinterpret_cast<const float4*>(s_sp)[lane];
            const float4 w2 = reinterpret_cast<const float4*>(s_w2)[lane];
            const __half* eprow = g_encproj + (size_t)b * TT * 128;
            for (int t = warp; t < TT; t += 8) {
                uint2 u = *(const uint2*)(eprow + t * 128 + lane * 4);
                float2 e0 = __half22float2(*reinterpret_cast<__half2*>(&u.x));
                float2 e1 = __half22float2(*reinterpret_cast<__half2*>(&u.y));
                float acc = fmaxf(e0.x + sp.x, 0.0f) * w2.x + fmaxf(e0.y + sp.y, 0.0f) * w2.y +
                            fmaxf(e1.x + sp.z, 0.0f) * w2.z + fmaxf(e1.y + sp.w, 0.0f) * w2.w;
#pragma unroll
                for (int o = 16; o > 0; o >>= 1) acc += __shfl_down_sync(0xffffffff, acc, o);
                if (lane == 0) s_sc[t] = acc;
            }
            __syncthreads();
        }

        // phase 2: softmax
        {
            float m = -1e30f;
            for (int t = tid; t < TT; t += 256) m = fmaxf(m, s_sc[t]);
            red[tid] = m;
            __syncthreads();
            for (int s = 128; s > 0; s >>= 1) {
                if (tid < s) red[tid] = fmaxf(red[tid], red[tid + s]);
                __syncthreads();
            }
            m = red[0];
            __syncthreads();
            float sum = 0.0f;
            for (int t = tid; t < TT; t += 256) {
                float e = expf(s_sc[t] - m);
                s_sc[t] = e;
                sum += e;
            }
            red[tid] = sum;
            __syncthreads();
            for (int s = 128; s > 0; s >>= 1) {
                if (tid < s) red[tid] += red[tid + s];
                __syncthreads();
            }
            const float inv = 1.0f / red[0];
            __syncthreads();
            for (int t = tid; t < TT; t += 256) s_sc[t] *= inv;
            __syncthreads();
        }

        // phase 3: weighted sum
        {
            const int grp = tid >> 6;
            const int l64 = tid & 63;
            const __half* erow = g_enc16 + (size_t)b * TT * 256;
            float4 a = make_float4(0.f, 0.f, 0.f, 0.f);
            for (int t = grp; t < TT; t += 4) {
                const float wt = s_sc[t];
                uint2 u = *(const uint2*)(erow + t * 256 + l64 * 4);
                float2 v0 = __half22float2(*reinterpret_cast<__half2*>(&u.x));
                float2 v1 = __half22float2(*reinterpret_cast<__half2*>(&u.y));
                a.x += wt * v0.x; a.y += wt * v0.y; a.z += wt * v1.x; a.w += wt * v1.y;
            }
            part[grp][l64 * 4 + 0] = a.x;
            part[grp][l64 * 4 + 1] = a.y;
            part[grp][l64 * 4 + 2] = a.z;
            part[grp][l64 * 4 + 3] = a.w;
            __syncthreads();
            const int d = tid;
            float vi = part[0][d] + part[1][d] + part[2][d] + part[3][d];
            split2(vi, g_xh_hi[b * 512 + d], g_xh_lo[b * 512 + d]);
            split2(s_state[d], g_xh_hi[b * 512 + 256 + d], g_xh_lo[b * 512 + 256 + d]);
        }
        gridbar();

        // === gates phase: 512x1024 = 512 tiles of 16x64, one per block, K=512 ===
        {
            const int m0 = (blk >> 4) * 16, n0 = (blk & 15) * 64;
            gemm_tile<0>(g_xh_hi, g_xh_lo, g_Wg_hi, g_Wg_lo, nullptr, g_gates,
                         nullptr, nullptr, m0, n0, 1024, 512, sred);
        }
        gridbar();
    }

    // ---- final LSTM cell (step 15) ----
    {
        const int j = tid;
        const float* gb = g_gates + (size_t)b * 1024;
        float gi = gb[j] + g_bg[j];
        float gf = gb[256 + j] + g_bg[256 + j];
        float gg = gb[512 + j] + g_bg[512 + j];
        float go = gb[768 + j] + g_bg[768 + j];
        float c = g_state[b * 512 + 256 + j];
        float cn = sigf(gf) * c + sigf(gi) * tanhf(gg);
        float hn = sigf(go) * tanhf(cn);
        const size_t o = (size_t)(NSTEPS - 1) * BATCH * 256 + b * 256 + j;
        split2(hn, g_outs_h[o], g_outs_l[o]);
    }
    gridbar();

    // ---- TD head: 8192x128, K=256 -> 1024 tiles, 2 per block ----
    for (int tt = blk; tt < 1024; tt += NB) {
        const int m0 = (tt >> 1) * 16, n0 = (tt & 1) * 64;
        gemm_tile<1>(g_outs_h, g_outs_l, g_wt1h, g_wt1l, bt1, g_td1, nullptr, nullptr,
                     m0, n0, 128, 256, sred);
    }
    gridbar();

    // ---- final dot: out[row] = td1[row] . Wt2 + bt2 (16 rows per block) ----
    {
        const float4 w2 = reinterpret_cast<const float4*>(Wt2)[lane];
        for (int rr = 0; rr < 2; rr++) {
            const int row = blk * 16 + warp * 2 + rr;
            float4 h = reinterpret_cast<const float4*>(g_td1 + (size_t)row * 128)[lane];
            float acc = h.x * w2.x + h.y * w2.y + h.z * w2.z + h.w * w2.w;
#pragma unroll
            for (int o = 16; o > 0; o >>= 1) acc += __shfl_down_sync(0xffffffff, acc, o);
            if (lane == 0) out[row] = acc + bt2[0];
        }
    }
}

// =============================== encfuse: enc_proj + fp16 transpose ===============================
// C[m,128] = enc[m,256] @ Wa1[:256]; also writes enc16[b,t,:] fp16 from loaded A tiles.
__global__ void encfuse(const float* __restrict__ A, const float* __restrict__ W,
                        __half* __restrict__ outp, __half* __restrict__ oute) {
    using namespace nvcuda;
    __shared__ __align__(16) char raw[36864];
    float* sA = (float*)raw;                // [2][64][20]
    float* sB = (float*)raw + 2 * 64 * 20;  // [2][16][132]
    const int tid = threadIdx.x;
    const int warp = tid >> 5, lane = tid & 31;
    const int wr = warp >> 2, wc = warp & 3;
    const int m0 = blockIdx.x * 64;
    const int ar = tid >> 2, ak = (tid & 3) * 4;
    const int bk = tid >> 5, bn = (tid & 31) * 4;
    const int am = m0 + ar;
    const int at = am >> 9, ab = am & 511;
    __half* eout = oute + ((size_t)ab * TT + at) * 256 + ak;

#define SAT(buf, m, k) (sA + ((buf)*64 + (m)) * 20 + (k))
#define SBT(buf, kk, n) (sB + ((buf)*16 + (kk)) * 132 + (n))

    wmma::fragment<wmma::accumulator, 16, 16, 8, float> acc[2][2];
#pragma unroll
    for (int i = 0; i < 2; i++)
#pragma unroll
        for (int j = 0; j < 2; j++) wmma::fill_fragment(acc[i][j], 0.0f);

    {
        float4 av = *(const float4*)(A + (size_t)am * 256 + ak);
        *(float4*)SAT(0, ar, ak) = av;
        *(__half2*)(eout) = __floats2half2_rn(av.x, av.y);
        *(__half2*)(eout + 2) = __floats2half2_rn(av.z, av.w);
    }
    *(float4*)SBT(0, bk, bn) = *(const float4*)(W + (size_t)bk * 128 + bn);
    *(float4*)SBT(0, bk + 8, bn) = *(const float4*)(W + (size_t)(bk + 8) * 128 + bn);
    __syncthreads();

    int buf = 0;
    for (int c = 0; c < 16; c++) {
        float4 pa, pb0, pb1;
        const bool pf = (c + 1 < 16);
        if (pf) {
            const int kb = (c + 1) << 4;
            pa = *(const float4*)(A + (size_t)am * 256 + kb + ak);
            pb0 = *(const float4*)(W + (size_t)(kb + bk) * 128 + bn);
            pb1 = *(const float4*)(W + (size_t)(kb + bk + 8) * 128 + bn);
            *(__half2*)(eout + kb) = __floats2half2_rn(pa.x, pa.y);
            *(__half2*)(eout + kb + 2) = __floats2half2_rn(pa.z, pa.w);
        }
#pragma unroll
        for (int ks = 0; ks < 16; ks += 8) {
            wmma::fragment<wmma::matrix_a, 16, 16, 8, wmma::precision::tf32, wmma::row_major> fa[2];
            wmma::fragment<wmma::matrix_b, 16, 16, 8, wmma::precision::tf32, wmma::row_major> fb[2];
#pragma unroll
            for (int i = 0; i < 2; i++) {
                wmma::load_matrix_sync(fa[i], SAT(buf, wr * 32 + i * 16, ks), 20);
#pragma unroll
                for (int e = 0; e < fa[i].num_elements; e++)
                    fa[i].x[e] = wmma::__float_to_tf32(fa[i].x[e]);
            }
#pragma unroll
            for (int j = 0; j < 2; j++) {
                wmma::load_matrix_sync(fb[j], SBT(buf, ks, wc * 32 + j * 16), 132);
#pragma unroll
                for (int e = 0; e < fb[j].num_elements; e++)
                    fb[j].x[e] = wmma::__float_to_tf32(fb[j].x[e]);
            }
#pragma unroll
            for (int i = 0; i < 2; i++)
#pragma unroll
                for (int j = 0; j < 2; j++) wmma::mma_sync(acc[i][j], fa[i], fb[j], acc[i][j]);
        }
        if (pf) {
            *(float4*)SAT(buf ^ 1, ar, ak) = pa;
            *(float4*)SBT(buf ^ 1, bk, bn) = pb0;
            *(float4*)SBT(buf ^ 1, bk + 8, bn) = pb1;
        }
        __syncthreads();
        buf ^= 1;
    }
#undef SAT
#undef SBT
    float* ep = (float*)raw + warp * (32 * 36);
#pragma unroll
    for (int i = 0; i < 2; i++)
#pragma unroll
        for (int j = 0; j < 2; j++)
            wmma::store_matrix_sync(ep + i * 16 * 36 + j * 16, acc[i][j], 36, wmma::mem_row_major);
    __syncwarp();
    for (int idx = lane; idx < 1024; idx += 32) {
        const int r = idx >> 5, cc = idx & 31;
        const int m = m0 + wr * 32 + r;
        const int t = m >> 9, b = m & 511;
        const int n = wc * 32 + cc;
        outp[((size_t)b * TT + t) * 128 + n] = __float2half(ep[r * 36 + cc]);
    }
}

// =============================== prep_all: every weight transform + x0 ===============================
__device__ __forceinline__ int cat_idx(const int* raw, int is64, int flat_idx) {
    return is64 ? raw[2 * flat_idx] : raw[flat_idx];
}

#define PB0 2048                 // Wg split
#define PB1 (PB0 + 1216)         // wc1
#define PB2 (PB1 + 768)          // wc2
#define PB3 (PB2 + 768)          // wc3
#define PB4 (PB3 + 128)          // wt1
#define PB5 (PB4 + 4)            // bg
#define PB6 (PB5 + 512)          // x0
#define PREP_GRID PB6

__global__ void prep_all(const float* __restrict__ Wih, const float* __restrict__ Whh,
                         const float* __restrict__ bih, const float* __restrict__ bhh,
                         const float* __restrict__ Wc1, const float* __restrict__ Wc2,
                         const float* __restrict__ Wc3, const float* __restrict__ Wt1,
                         const int* __restrict__ xcat_raw, const float* __restrict__ sh,
                         const float* __restrict__ sc, const float* __restrict__ es,
                         const float* __restrict__ ei, const float* __restrict__ ef) {
    const int blk = blockIdx.x;
    const int tid = threadIdx.x;
    if (blk < PB0) {
        int idx = blk * 256 + tid;
        int k = idx >> 10, n = idx & 1023;
        float v = (k < 256) ? Wih[n * 256 + k] : Whh[n * 256 + (k - 256)];
        split2(v, g_Wg_hi[idx], g_Wg_lo[idx]);
    } else if (blk < PB1) {
        int idx = (blk - PB0) * 256 + tid;
        split2(Wc1[idx], g_wc1h[idx], g_wc1l[idx]);
    } else if (blk < PB2) {
        int idx = (blk - PB1) * 256 + tid;
        split2(Wc2[idx], g_wc2h[idx], g_wc2l[idx]);
    } else if (blk < PB3) {
        int idx = (blk - PB2) * 256 + tid;
        split2(Wc3[idx], g_wc3h[idx], g_wc3l[idx]);
    } else if (blk < PB4) {
        int idx = (blk - PB3) * 256 + tid;
        split2(Wt1[idx], g_wt1h[idx], g_wt1l[idx]);
    } else if (blk < PB5) {
        int idx = (blk - PB4) * 256 + tid;
        g_bg[idx] = bih[idx] + bhh[idx];
    } else {
        const int b = blk - PB5;
        __shared__ int s_is64;
        if (tid == 0) {
            int is64 = 1;
            for (int i = 0; i < 32; i++)
                if (xcat_raw[2 * i + 1] != 0) { is64 = 0; break; }
            s_is64 = is64;
        }
        __syncthreads();
        const int is64 = s_is64;
        for (int t = tid; t < 608; t += 256) {
            float v;
            if (t < 16) {
                int i0 = min(max(cat_idx(xcat_raw, is64, b * 3 + 0), 0), 53);
                v = es[(size_t)i0 * 16 + t];
            } else if (t < 80) {
                int i1 = min(max(cat_idx(xcat_raw, is64, b * 3 + 1), 0), 4035);
                v = ei[(size_t)i1 * 64 + (t - 16)];
            } else if (t < 96) {
                int i2 = min(max(cat_idx(xcat_raw, is64, b * 3 + 2), 0), 32);
                v = ef[(size_t)i2 * 16 + (t - 80)];
            } else if (t < 352) {
                v = sh[b * 256 + (t - 96)];
            } else {
                v = sc[b * 256 + (t - 352)];
            }
            split2(v, g_x0h[b * 608 + t], g_x0l[b * 608 + t]);
        }
    }
}

// ---------------- host orchestration: 3 launches ----------------
extern "C" void kernel_launch(void* const* d_in, const int* in_sizes, int n_in,
                              void* d_out, int out_size) {
    (void)in_sizes; (void)n_in; (void)out_size;
    const int*   xcat    = (const int*)d_in[0];
    const float* state_h = (const float*)d_in[1];
    const float* state_c = (const float*)d_in[2];
    const float* enc     = (const float*)d_in[3];
    const float* es      = (const float*)d_in[4];
    const float* ei      = (const float*)d_in[5];
    const float* ef      = (const float*)d_in[6];
    const float* Wc1 = (const float*)d_in[7];  const float* bc1 = (const float*)d_in[8];
    const float* Wc2 = (const float*)d_in[9];  const float* bc2 = (const float*)d_in[10];
    const float* Wc3 = (const float*)d_in[11]; const float* bc3 = (const float*)d_in[12];
    const float* Wa1 = (const float*)d_in[13]; const float* ba1 = (const float*)d_in[14];
    const float* Wa2 = (const float*)d_in[15]; // ba2 unused (softmax-invariant)
    const float* Wt1 = (const float*)d_in[17]; const float* bt1 = (const float*)d_in[18];
    const float* Wt2 = (const float*)d_in[19]; const float* bt2 = (const float*)d_in[20];
    const float* Wih = (const float*)d_in[21]; const float* Whh = (const float*)d_in[22];
    const float* bih = (const float*)d_in[23]; const float* bhh = (const float*)d_in[24];
    float* out = (float*)d_out;

    __half *p_encproj, *p_enc16;
    cudaGetSymbolAddress((void**)&p_encproj, g_encproj);
    cudaGetSymbolAddress((void**)&p_enc16, g_enc16);

    prep_all<<<PREP_GRID, 256>>>(Wih, Whh, bih, bhh, Wc1, Wc2, Wc3, Wt1,
                                 xcat, state_h, state_c, es, ei, ef);
    encfuse<<<TT * BATCH / 64, 256>>>(enc, Wa1, p_encproj, p_enc16);
    decode_kernel<<<NB, 256>>>(Wa1 + 256 * 128, ba1, Wa2, bc1, bc2, bc3, bt1, Wt2, bt2, out);
}

// round 17
// speedup vs baseline: 1.0013x; 1.0013x over previous
#include <cuda_runtime.h>
#include <cuda_bf16.h>
#include <cuda_fp16.h>
#include <mma.h>
#include <cstdint>

#define BATCH 512
#define TT 365
#define DD 256
#define NSTEPS 16
#define NB 512   // decode grid size (== BATCH)

// ---------------- scratch (device globals; no allocation allowed) ----------------
__device__ __nv_bfloat16 g_x0h[BATCH * 608], g_x0l[BATCH * 608];
__device__ __nv_bfloat16 g_a1h[BATCH * 512], g_a1l[BATCH * 512];
__device__ __nv_bfloat16 g_a2h[BATCH * 384], g_a2l[BATCH * 384];
__device__ float g_state[BATCH * 512];                       // [h | c] fp32
__device__ __half g_encproj[(size_t)TT * BATCH * 128];       // [B,T,128] fp16
__device__ __half g_enc16[(size_t)TT * BATCH * 256];         // [B,T,256] fp16
__device__ __nv_bfloat16 g_xh_hi[BATCH * 512], g_xh_lo[BATCH * 512];   // [inp|h]
__device__ __nv_bfloat16 g_Wg_hi[512 * 1024], g_Wg_lo[512 * 1024];     // [Wih^T;Whh^T]
__device__ __nv_bfloat16 g_wc1h[608 * 512], g_wc1l[608 * 512];
__device__ __nv_bfloat16 g_wc2h[512 * 384], g_wc2l[512 * 384];
__device__ __nv_bfloat16 g_wc3h[384 * 512], g_wc3l[384 * 512];
__device__ __nv_bfloat16 g_wt1h[256 * 128], g_wt1l[256 * 128];
__device__ float g_bg[1024];
__device__ float g_gates[BATCH * 1024];
__device__ __nv_bfloat16 g_outs_h[NSTEPS * BATCH * 256], g_outs_l[NSTEPS * BATCH * 256];
__device__ float g_td1[NSTEPS * BATCH * 128];

// grid barrier state
__device__ unsigned g_bar_cnt;
__device__ volatile unsigned g_bar_gen;

__device__ __forceinline__ float sigf(float x) { return 1.0f / (1.0f + expf(-x)); }

__device__ __forceinline__ void split2(float v, __nv_bfloat16& hi, __nv_bfloat16& lo) {
    hi = __float2bfloat16(v);
    lo = __float2bfloat16(v - __bfloat162float(hi));
}

// ---------------- grid-wide barrier (all NB blocks co-resident) ----------------
__device__ __forceinline__ void gridbar() {
    __threadfence();
    __syncthreads();
    if (threadIdx.x == 0) {
        unsigned gen = g_bar_gen;
        if (atomicInc(&g_bar_cnt, NB - 1) == NB - 1) {
            __threadfence();
            g_bar_gen = gen + 1;
        } else {
            while (g_bar_gen == gen) __nanosleep(128);
        }
        __threadfence();
    }
    __syncthreads();
}

// ======== per-block 16x64 split-bf16 warp-tile GEMM (global operands, L2-hot) ========
// 8 warps: q = warp&3 -> 16-col slice, h = warp>>2 -> K half. sred = 8*256 floats smem.
template <int ACT>
__device__ void gemm_tile(const __nv_bfloat16* __restrict__ Ah, const __nv_bfloat16* __restrict__ Al,
                          const __nv_bfloat16* __restrict__ Wh, const __nv_bfloat16* __restrict__ Wl,
                          const float* __restrict__ bias, float* __restrict__ Cf,
                          __nv_bfloat16* __restrict__ Chi, __nv_bfloat16* __restrict__ Clo,
                          int m0, int n0, int N, int K, float* sred) {
    using namespace nvcuda;
    const int warp = threadIdx.x >> 5;
    const int q = warp & 3, h = warp >> 2;
    const int n1 = n0 + q * 16;
    const int khalf = K >> 1;
    const int kbeg = h * khalf;
    wmma::fragment<wmma::accumulator, 16, 16, 16, float> acc;
    wmma::fill_fragment(acc, 0.0f);
    for (int k = kbeg; k < kbeg + khalf; k += 16) {
        wmma::fragment<wmma::matrix_a, 16, 16, 16, __nv_bfloat16, wmma::row_major> fah, fal;
        wmma::fragment<wmma::matrix_b, 16, 16, 16, __nv_bfloat16, wmma::row_major> fbh, fbl;
        wmma::load_matrix_sync(fah, Ah + (size_t)m0 * K + k, K);
        wmma::load_matrix_sync(fal, Al + (size_t)m0 * K + k, K);
        wmma::load_matrix_sync(fbh, Wh + (size_t)k * N + n1, N);
        wmma::load_matrix_sync(fbl, Wl + (size_t)k * N + n1, N);
        wmma::mma_sync(acc, fah, fbh, acc);
        wmma::mma_sync(acc, fah, fbl, acc);
        wmma::mma_sync(acc, fal, fbh, acc);
    }
    wmma::store_matrix_sync(sred + warp * 256, acc, 16, wmma::mem_row_major);
    __syncthreads();
    for (int idx = threadIdx.x; idx < 1024; idx += 256) {
        const int r = idx >> 6, c = idx & 63;
        const int qq = c >> 4, cc = c & 15;
        float v = sred[qq * 256 + r * 16 + cc] + sred[(4 + qq) * 256 + r * 16 + cc];
        if (bias) v += bias[n0 + c];
        if (ACT) v = fmaxf(v, 0.0f);
        const size_t off = (size_t)(m0 + r) * N + n0 + c;
        if (Cf) Cf[off] = v;
        if (Chi) {
            __nv_bfloat16 hi, lo;
            split2(v, hi, lo);
            Chi[off] = hi;
            Clo[off] = lo;
        }
    }
    __syncthreads();
}

// =============================== THE persistent decode kernel ===============================
__global__ void __launch_bounds__(256, 4)
decode_kernel(const float* __restrict__ Wa1s, const float* __restrict__ ba1,
              const float* __restrict__ Wa2, const float* __restrict__ bc1,
              const float* __restrict__ bc2, const float* __restrict__ bc3,
              const float* __restrict__ bt1, const float* __restrict__ Wt2,
              const float* __restrict__ bt2, float* __restrict__ out) {
    const int blk = blockIdx.x;
    const int tid = threadIdx.x;
    const int warp = tid >> 5;
    const int lane = tid & 31;

    __shared__ float sred[8 * 256];      // gemm reduction (8 KB)
    __shared__ float s_state[512];
    __shared__ float s_sp[128];
    __shared__ float s_w2[128];
    __shared__ float s_sc[368];
    __shared__ float red[256];
    __shared__ float part[4][256];

    // ---- ct chain: ct1 (512x512 K=608 relu), ct2 (512x384 K=512 relu), ct3 (512x512 K=384) ----
    if (blk < 256) {
        const int m0 = (blk >> 3) * 16, n0 = (blk & 7) * 64;
        gemm_tile<1>(g_x0h, g_x0l, g_wc1h, g_wc1l, bc1, nullptr, g_a1h, g_a1l,
                     m0, n0, 512, 608, sred);
    }
    gridbar();
    if (blk < 192) {
        const int m0 = (blk / 6) * 16, n0 = (blk % 6) * 64;
        gemm_tile<1>(g_a1h, g_a1l, g_wc2h, g_wc2l, bc2, nullptr, g_a2h, g_a2l,
                     m0, n0, 384, 512, sred);
    }
    gridbar();
    if (blk < 256) {
        const int m0 = (blk >> 3) * 16, n0 = (blk & 7) * 64;
        gemm_tile<0>(g_a2h, g_a2l, g_wc3h, g_wc3l, bc3, g_state, nullptr, nullptr,
                     m0, n0, 512, 384, sred);
    }
    gridbar();

    // ---- 16 decode steps ----
    const int b = blk;  // attn block == batch row
    for (int step = 0; step < NSTEPS; step++) {
        // === attn phase (incl. fused LSTM cell for step-1) ===
        if (step > 0) {
            const int j = tid;
            const float* gb = g_gates + (size_t)b * 1024;
            float gi = gb[j] + g_bg[j];
            float gf = gb[256 + j] + g_bg[256 + j];
            float gg = gb[512 + j] + g_bg[512 + j];
            float go = gb[768 + j] + g_bg[768 + j];
            float c = g_state[b * 512 + 256 + j];
            float cn = sigf(gf) * c + sigf(gi) * tanhf(gg);
            float hn = sigf(go) * tanhf(cn);
            s_state[j] = hn;
            s_state[256 + j] = cn;
            g_state[b * 512 + j] = hn;
            g_state[b * 512 + 256 + j] = cn;
            const size_t o = (size_t)(step - 1) * BATCH * 256 + b * 256 + j;
            split2(hn, g_outs_h[o], g_outs_l[o]);
        } else {
            s_state[tid] = g_state[b * 512 + tid];
            s_state[256 + tid] = g_state[b * 512 + 256 + tid];
        }
        if (tid < 128) s_w2[tid] = Wa2[tid];
        __syncthreads();

        // phase 0: sproj[d] = sum_k state[k] * Wa1s[k,d] + ba1[d]
        {
            const int d = tid & 127;
            const int half_ = tid >> 7;
            const float* wp = Wa1s + (size_t)(half_ * 256) * 128 + d;
            const float* st = s_state + half_ * 256;
            float acc = 0.0f;
#pragma unroll 16
            for (int k = 0; k < 256; k++) acc += st[k] * wp[(size_t)k * 128];
            red[tid] = acc;
            __syncthreads();
            if (tid < 128) s_sp[tid] = red[tid] + red[tid + 128] + ba1[tid];
            __syncthreads();
        }

        // phase 1: scores
        {
            const float4 sp = reinterpret_cast<const float4*>(s_sp)[lane];
            const float4 w2 = reinterpret_cast<const float4*>(s_w2)[lane];
            const __half* eprow = g_encproj + (size_t)b * TT * 128;
            for (int t = warp; t < TT; t += 8) {
                uint2 u = *(const uint2*)(eprow + t * 128 + lane * 4);
                float2 e0 = __half22float2(*reinterpret_cast<__half2*>(&u.x));
                float2 e1 = __half22float2(*reinterpret_cast<__half2*>(&u.y));
                float acc = fmaxf(e0.x + sp.x, 0.0f) * w2.x + fmaxf(e0.y + sp.y, 0.0f) * w2.y +
                            fmaxf(e1.x + sp.z, 0.0f) * w2.z + fmaxf(e1.y + sp.w, 0.0f) * w2.w;
#pragma unroll
                for (int o = 16; o > 0; o >>= 1) acc += __shfl_down_sync(0xffffffff, acc, o);
                if (lane == 0) s_sc[t] = acc;
            }
            __syncthreads();
        }

        // phase 2: softmax
        {
            float m = -1e30f;
            for (int t = tid; t < TT; t += 256) m = fmaxf(m, s_sc[t]);
            red[tid] = m;
            __syncthreads();
            for (int s = 128; s > 0; s >>= 1) {
                if (tid < s) red[tid] = fmaxf(red[tid], red[tid + s]);
                __syncthreads();
            }
            m = red[0];
            __syncthreads();
            float sum = 0.0f;
            for (int t = tid; t < TT; t += 256) {
                float e = expf(s_sc[t] - m);
                s_sc[t] = e;
                sum += e;
            }
            red[tid] = sum;
            __syncthreads();
            for (int s = 128; s > 0; s >>= 1) {
                if (tid < s) red[tid] += red[tid + s];
                __syncthreads();
            }
            const float inv = 1.0f / red[0];
            __syncthreads();
            for (int t = tid; t < TT; t += 256) s_sc[t] *= inv;
            __syncthreads();
        }

        // phase 3: weighted sum
        {
            const int grp = tid >> 6;
            const int l64 = tid & 63;
            const __half* erow = g_enc16 + (size_t)b * TT * 256;
            float4 a = make_float4(0.f, 0.f, 0.f, 0.f);
            for (int t = grp; t < TT; t += 4) {
                const float wt = s_sc[t];
                uint2 u = *(const uint2*)(erow + t * 256 + l64 * 4);
                float2 v0 = __half22float2(*reinterpret_cast<__half2*>(&u.x));
                float2 v1 = __half22float2(*reinterpret_cast<__half2*>(&u.y));
                a.x += wt * v0.x; a.y += wt * v0.y; a.z += wt * v1.x; a.w += wt * v1.y;
            }
            part[grp][l64 * 4 + 0] = a.x;
            part[grp][l64 * 4 + 1] = a.y;
            part[grp][l64 * 4 + 2] = a.z;
            part[grp][l64 * 4 + 3] = a.w;
            __syncthreads();
            const int d = tid;
            float vi = part[0][d] + part[1][d] + part[2][d] + part[3][d];
            split2(vi, g_xh_hi[b * 512 + d], g_xh_lo[b * 512 + d]);
            split2(s_state[d], g_xh_hi[b * 512 + 256 + d], g_xh_lo[b * 512 + 256 + d]);
        }
        gridbar();

        // === gates phase: 512x1024 = 512 tiles of 16x64, one per block, K=512 ===
        {
            const int m0 = (blk >> 4) * 16, n0 = (blk & 15) * 64;
            gemm_tile<0>(g_xh_hi, g_xh_lo, g_Wg_hi, g_Wg_lo, nullptr, g_gates,
                         nullptr, nullptr, m0, n0, 1024, 512, sred);
        }
        gridbar();
    }

    // ---- final LSTM cell (step 15) ----
    {
        const int j = tid;
        const float* gb = g_gates + (size_t)b * 1024;
        float gi = gb[j] + g_bg[j];
        float gf = gb[256 + j] + g_bg[256 + j];
        float gg = gb[512 + j] + g_bg[512 + j];
        float go = gb[768 + j] + g_bg[768 + j];
        float c = g_state[b * 512 + 256 + j];
        float cn = sigf(gf) * c + sigf(gi) * tanhf(gg);
        float hn = sigf(go) * tanhf(cn);
        const size_t o = (size_t)(NSTEPS - 1) * BATCH * 256 + b * 256 + j;
        split2(hn, g_outs_h[o], g_outs_l[o]);
    }
    gridbar();

    // ---- TD head: 8192x128, K=256 -> 1024 tiles, 2 per block ----
    for (int tt = blk; tt < 1024; tt += NB) {
        const int m0 = (tt >> 1) * 16, n0 = (tt & 1) * 64;
        gemm_tile<1>(g_outs_h, g_outs_l, g_wt1h, g_wt1l, bt1, g_td1, nullptr, nullptr,
                     m0, n0, 128, 256, sred);
    }
    gridbar();

    // ---- final dot: out[row] = td1[row] . Wt2 + bt2 (16 rows per block) ----
    {
        const float4 w2 = reinterpret_cast<const float4*>(Wt2)[lane];
        for (int rr = 0; rr < 2; rr++) {
            const int row = blk * 16 + warp * 2 + rr;
            float4 h = reinterpret_cast<const float4*>(g_td1 + (size_t)row * 128)[lane];
            float acc = h.x * w2.x + h.y * w2.y + h.z * w2.z + h.w * w2.w;
#pragma unroll
            for (int o = 16; o > 0; o >>= 1) acc += __shfl_down_sync(0xffffffff, acc, o);
            if (lane == 0) out[row] = acc + bt2[0];
        }
    }
}

// =============================== encfuse: enc_proj + fp16 transpose ===============================
// C[m,128] = enc[m,256] @ Wa1[:256]; also writes enc16[b,t,:] fp16 from loaded A tiles.
__global__ void encfuse(const float* __restrict__ A, const float* __restrict__ W,
                        __half* __restrict__ outp, __half* __restrict__ oute) {
    using namespace nvcuda;
    __shared__ __align__(16) char raw[36864];
    float* sA = (float*)raw;                // [2][64][20]
    float* sB = (float*)raw + 2 * 64 * 20;  // [2][16][132]
    const int tid = threadIdx.x;
    const int warp = tid >> 5, lane = tid & 31;
    const int wr = warp >> 2, wc = warp & 3;
    const int m0 = blockIdx.x * 64;
    const int ar = tid >> 2, ak = (tid & 3) * 4;
    const int bk = tid >> 5, bn = (tid & 31) * 4;
    const int am = m0 + ar;
    const int at = am >> 9, ab = am & 511;
    __half* eout = oute + ((size_t)ab * TT + at) * 256 + ak;

#define SAT(buf, m, k) (sA + ((buf)*64 + (m)) * 20 + (k))
#define SBT(buf, kk, n) (sB + ((buf)*16 + (kk)) * 132 + (n))

    wmma::fragment<wmma::accumulator, 16, 16, 8, float> acc[2][2];
#pragma unroll
    for (int i = 0; i < 2; i++)
#pragma unroll
        for (int j = 0; j < 2; j++) wmma::fill_fragment(acc[i][j], 0.0f);

    {
        float4 av = *(const float4*)(A + (size_t)am * 256 + ak);
        *(float4*)SAT(0, ar, ak) = av;
        *(__half2*)(eout) = __floats2half2_rn(av.x, av.y);
        *(__half2*)(eout + 2) = __floats2half2_rn(av.z, av.w);
    }
    *(float4*)SBT(0, bk, bn) = *(const float4*)(W + (size_t)bk * 128 + bn);
    *(float4*)SBT(0, bk + 8, bn) = *(const float4*)(W + (size_t)(bk + 8) * 128 + bn);
    __syncthreads();

    int buf = 0;
    for (int c = 0; c < 16; c++) {
        float4 pa, pb0, pb1;
        const bool pf = (c + 1 < 16);
        if (pf) {
            const int kb = (c + 1) << 4;
            pa = *(const float4*)(A + (size_t)am * 256 + kb + ak);
            pb0 = *(const float4*)(W + (size_t)(kb + bk) * 128 + bn);
            pb1 = *(const float4*)(W + (size_t)(kb + bk + 8) * 128 + bn);
            *(__half2*)(eout + kb) = __floats2half2_rn(pa.x, pa.y);
            *(__half2*)(eout + kb + 2) = __floats2half2_rn(pa.z, pa.w);
        }
#pragma unroll
        for (int ks = 0; ks < 16; ks += 8) {
            wmma::fragment<wmma::matrix_a, 16, 16, 8, wmma::precision::tf32, wmma::row_major> fa[2];
            wmma::fragment<wmma::matrix_b, 16, 16, 8, wmma::precision::tf32, wmma::row_major> fb[2];
#pragma unroll
            for (int i = 0; i < 2; i++) {
                wmma::load_matrix_sync(fa[i], SAT(buf, wr * 32 + i * 16, ks), 20);
#pragma unroll
                for (int e = 0; e < fa[i].num_elements; e++)
                    fa[i].x[e] = wmma::__float_to_tf32(fa[i].x[e]);
            }
#pragma unroll
            for (int j = 0; j < 2; j++) {
                wmma::load_matrix_sync(fb[j], SBT(buf, ks, wc * 32 + j * 16), 132);
#pragma unroll
                for (int e = 0; e < fb[j].num_elements; e++)
                    fb[j].x[e] = wmma::__float_to_tf32(fb[j].x[e]);
            }
#pragma unroll
            for (int i = 0; i < 2; i++)
#pragma unroll
                for (int j = 0; j < 2; j++) wmma::mma_sync(acc[i][j], fa[i], fb[j], acc[i][j]);
        }
        if (pf) {
            *(float4*)SAT(buf ^ 1, ar, ak) = pa;
            *(float4*)SBT(buf ^ 1, bk, bn) = pb0;
            *(float4*)SBT(buf ^ 1, bk + 8, bn) = pb1;
        }
        __syncthreads();
        buf ^= 1;
    }
#undef SAT
#undef SBT
    float* ep = (float*)raw + warp * (32 * 36);
#pragma unroll
    for (int i = 0; i < 2; i++)
#pragma unroll
        for (int j = 0; j < 2; j++)
            wmma::store_matrix_sync(ep + i * 16 * 36 + j * 16, acc[i][j], 36, wmma::mem_row_major);
    __syncwarp();
    for (int idx = lane; idx < 1024; idx += 32) {
        const int r = idx >> 5, cc = idx & 31;
        const int m = m0 + wr * 32 + r;
        const int t = m >> 9, b = m & 511;
        const int n = wc * 32 + cc;
        outp[((size_t)b * TT + t) * 128 + n] = __float2half(ep[r * 36 + cc]);
    }
}

// =============================== prep_all: every weight transform + x0 ===============================
__device__ __forceinline__ int cat_idx(const int* raw, int is64, int flat_idx) {
    return is64 ? raw[2 * flat_idx] : raw[flat_idx];
}

#define PB0 2048                 // Wg split
#define PB1 (PB0 + 1216)         // wc1
#define PB2 (PB1 + 768)          // wc2
#define PB3 (PB2 + 768)          // wc3
#define PB4 (PB3 + 128)          // wt1
#define PB5 (PB4 + 4)            // bg
#define PB6 (PB5 + 512)          // x0
#define PREP_GRID PB6

__global__ void prep_all(const float* __restrict__ Wih, const float* __restrict__ Whh,
                         const float* __restrict__ bih, const float* __restrict__ bhh,
                         const float* __restrict__ Wc1, const float* __restrict__ Wc2,
                         const float* __restrict__ Wc3, const float* __restrict__ Wt1,
                         const int* __restrict__ xcat_raw, const float* __restrict__ sh,
                         const float* __restrict__ sc, const float* __restrict__ es,
                         const float* __restrict__ ei, const float* __restrict__ ef) {
    const int blk = blockIdx.x;
    const int tid = threadIdx.x;
    if (blk < PB0) {
        int idx = blk * 256 + tid;
        int k = idx >> 10, n = idx & 1023;
        float v = (k < 256) ? Wih[n * 256 + k] : Whh[n * 256 + (k - 256)];
        split2(v, g_Wg_hi[idx], g_Wg_lo[idx]);
    } else if (blk < PB1) {
        int idx = (blk - PB0) * 256 + tid;
        split2(Wc1[idx], g_wc1h[idx], g_wc1l[idx]);
    } else if (blk < PB2) {
        int idx = (blk - PB1) * 256 + tid;
        split2(Wc2[idx], g_wc2h[idx], g_wc2l[idx]);
    } else if (blk < PB3) {
        int idx = (blk - PB2) * 256 + tid;
        split2(Wc3[idx], g_wc3h[idx], g_wc3l[idx]);
    } else if (blk < PB4) {
        int idx = (blk - PB3) * 256 + tid;
        split2(Wt1[idx], g_wt1h[idx], g_wt1l[idx]);
    } else if (blk < PB5) {
        int idx = (blk - PB4) * 256 + tid;
        g_bg[idx] = bih[idx] + bhh[idx];
    } else {
        const int b = blk - PB5;
        __shared__ int s_is64;
        if (tid == 0) {
            int is64 = 1;
            for (int i = 0; i < 32; i++)
                if (xcat_raw[2 * i + 1] != 0) { is64 = 0; break; }
            s_is64 = is64;
        }
        __syncthreads();
        const int is64 = s_is64;
        for (int t = tid; t < 608; t += 256) {
            float v;
            if (t < 16) {
                int i0 = min(max(cat_idx(xcat_raw, is64, b * 3 + 0), 0), 53);
                v = es[(size_t)i0 * 16 + t];
            } else if (t < 80) {
                int i1 = min(max(cat_idx(xcat_raw, is64, b * 3 + 1), 0), 4035);
                v = ei[(size_t)i1 * 64 + (t - 16)];
            } else if (t < 96) {
                int i2 = min(max(cat_idx(xcat_raw, is64, b * 3 + 2), 0), 32);
                v = ef[(size_t)i2 * 16 + (t - 80)];
            } else if (t < 352) {
                v = sh[b * 256 + (t - 96)];
            } else {
                v = sc[b * 256 + (t - 352)];
            }
            split2(v, g_x0h[b * 608 + t], g_x0l[b * 608 + t]);
        }
    }
}

// ---------------- host orchestration: 3 launches ----------------
extern "C" void kernel_launch(void* const* d_in, const int* in_sizes, int n_in,
                              void* d_out, int out_size) {
    (void)in_sizes; (void)n_in; (void)out_size;
    const int*   xcat    = (const int*)d_in[0];
    const float* state_h = (const float*)d_in[1];
    const float* state_c = (const float*)d_in[2];
    const float* enc     = (const float*)d_in[3];
    const float* es      = (const float*)d_in[4];
    const float* ei      = (const float*)d_in[5];
    const float* ef      = (const float*)d_in[6];
    const float* Wc1 = (const float*)d_in[7];  const float* bc1 = (const float*)d_in[8];
    const float* Wc2 = (const float*)d_in[9];  const float* bc2 = (const float*)d_in[10];
    const float* Wc3 = (const float*)d_in[11]; const float* bc3 = (const float*)d_in[12];
    const float* Wa1 = (const float*)d_in[13]; const float* ba1 = (const float*)d_in[14];
    const float* Wa2 = (const float*)d_in[15]; // ba2 unused (softmax-invariant)
    const float* Wt1 = (const float*)d_in[17]; const float* bt1 = (const float*)d_in[18];
    const float* Wt2 = (const float*)d_in[19]; const float* bt2 = (const float*)d_in[20];
    const float* Wih = (const float*)d_in[21]; const float* Whh = (const float*)d_in[22];
    const float* bih = (const float*)d_in[23]; const float* bhh = (const float*)d_in[24];
    float* out = (float*)d_out;

    __half *p_encproj, *p_enc16;
    cudaGetSymbolAddress((void**)&p_encproj, g_encproj);
    cudaGetSymbolAddress((void**)&p_enc16, g_enc16);

    prep_all<<<PREP_GRID, 256>>>(Wih, Whh, bih, bhh, Wc1, Wc2, Wc3, Wt1,
                                 xcat, state_h, state_c, es, ei, ef);
    encfuse<<<TT * BATCH / 64, 256>>>(enc, Wa1, p_encproj, p_enc16);
    decode_kernel<<<NB, 256>>>(Wa1 + 256 * 128, ba1, Wa2, bc1, bc2, bc3, bt1, Wt2, bt2, out);
}